// round 5
// baseline (speedup 1.0000x reference)
#include <cuda_runtime.h>
#include <cuda_bf16.h>
#include <cstdint>
#include <math.h>

#define B_ 64
#define S_ 2048
#define H_ 512
#define F_ 128

// ---------------- persistent device scratch (no allocations allowed) -------
__device__ __nv_bfloat16 g_WencHi[H_ * H_];   // [n][k] transposed, k contiguous
__device__ __nv_bfloat16 g_WencLo[H_ * H_];
__device__ __nv_bfloat16 g_WzHi[H_ * F_];     // [n][k], k (=f) contiguous
__device__ __nv_bfloat16 g_WzLo[H_ * F_];
__device__ float g_proj_a[B_ * H_];
__device__ float g_proj_b[B_ * H_];
__device__ float g_scores[B_ * S_];
__device__ float g_wcpart[8 * B_ * H_];       // weighted-context partials [8][B][H]

// ---------------- helpers --------------------------------------------------
static __device__ __forceinline__ void mma_bf16(float d[4], const unsigned a[4],
                                                const unsigned b[2]) {
    asm volatile(
        "mma.sync.aligned.m16n8k16.row.col.f32.bf16.bf16.f32 "
        "{%0,%1,%2,%3}, {%4,%5,%6,%7}, {%8,%9}, {%0,%1,%2,%3};\n"
        : "+f"(d[0]), "+f"(d[1]), "+f"(d[2]), "+f"(d[3])
        : "r"(a[0]), "r"(a[1]), "r"(a[2]), "r"(a[3]), "r"(b[0]), "r"(b[1]));
}

static __device__ __forceinline__ void cp_async16(void* smem_dst, const void* gmem_src) {
    unsigned d = (unsigned)__cvta_generic_to_shared(smem_dst);
    asm volatile("cp.async.cg.shared.global [%0], [%1], 16;\n" ::"r"(d), "l"(gmem_src));
}
static __device__ __forceinline__ void cp_commit() {
    asm volatile("cp.async.commit_group;\n" ::: "memory");
}
static __device__ __forceinline__ void cp_wait0() {
    asm volatile("cp.async.wait_group 0;\n" ::: "memory");
}
static __device__ __forceinline__ void cp_wait1() {
    asm volatile("cp.async.wait_group 1;\n" ::: "memory");
}

static __device__ __forceinline__ void split_bf16(float x, __nv_bfloat16& hi,
                                                  __nv_bfloat16& lo) {
    hi = __float2bfloat16_rn(x);
    lo = __float2bfloat16_rn(x - __bfloat162float(hi));
}

// ---------------- kernel 1: split + transpose weights, zero wc partials ----
__global__ void prep_kernel(const float* __restrict__ Wenc,
                            const float* __restrict__ Wz) {
    int idx = blockIdx.x * 256 + threadIdx.x;      // grid: 1024x256 = 262144 = 512*512
    {
        float w = Wenc[idx];                       // [k][n] row-major, idx = k*512+n
        __nv_bfloat16 hi, lo;
        split_bf16(w, hi, lo);
        int k = idx >> 9, n = idx & 511;
        g_WencHi[n * H_ + k] = hi;
        g_WencLo[n * H_ + k] = lo;
    }
    if (idx < F_ * H_) {                           // Wz [f][n], idx = f*512+n
        float w = Wz[idx];
        __nv_bfloat16 hi, lo;
        split_bf16(w, hi, lo);
        int f = idx >> 9, n = idx & 511;
        g_WzHi[n * F_ + f] = hi;
        g_WzLo[n * F_ + f] = lo;
    }
    g_wcpart[idx] = 0.0f;                          // 8*64*512 = 262144 exactly
}

// ---------------- kernel 2: proj_in_a / proj_in_b (tiny fp32 GEMV) ---------
__global__ void proj_in_kernel(const float* __restrict__ input,
                               const float* __restrict__ W_a,
                               const float* __restrict__ b_a,
                               const float* __restrict__ W_b,
                               const float* __restrict__ b_b) {
    __shared__ float x[H_];
    int b = blockIdx.x, tid = threadIdx.x;         // 256 threads
    x[tid] = input[b * H_ + tid];
    x[tid + 256] = input[b * H_ + tid + 256];
    __syncthreads();
    for (int h = tid; h < H_; h += 256) {
        float aa = 0.f, ab = 0.f;
#pragma unroll 8
        for (int j = 0; j < H_; ++j) {
            float xv = x[j];
            aa += xv * W_a[j * H_ + h];
            ab += xv * W_b[j * H_ + h];
        }
        g_proj_a[b * H_ + h] = tanhf(aa + b_a[h]);
        g_proj_b[b * H_ + h] = tanhf(ab + b_b[h]);
    }
}

// ---------------- kernel 3/4: fused  score = sum_h tanh(A@W + bias) * avec -
// bf16 split-precision (hi*hi + hi*lo + lo*hi) via mma.sync m16n8k16.
// Block = 64 rows of one batch, BN=128 column tile, BK=32, double-buffered W.
template <int K, int ADD>
__global__ void __launch_bounds__(256, 1)
score_kernel(const float* __restrict__ Ag,        // [B][S][K]
             const float* __restrict__ bias) {    // [H]
    constexpr int AS = K + 8;                     // padded smem stride (conflict-free)
    constexpr int KT = K / 32;
    extern __shared__ char smem_raw[];
    __nv_bfloat16* Ahi = (__nv_bfloat16*)smem_raw;
    __nv_bfloat16* Alo = Ahi + 64 * AS;
    __nv_bfloat16* Bhs = Alo + 64 * AS;           // [2][128][40]
    __nv_bfloat16* Bls = Bhs + 2 * 128 * 40;
    float* ssc = (float*)(Bls + 2 * 128 * 40);    // [64]

    const __nv_bfloat16* __restrict__ Whi = (K == H_) ? g_WencHi : g_WzHi;
    const __nv_bfloat16* __restrict__ Wlo = (K == H_) ? g_WencLo : g_WzLo;
    const float* __restrict__ avec =
        ((K == H_) ? g_proj_a : g_proj_b) + (blockIdx.x >> 5) * H_;

    int tid = threadIdx.x;
    int b = blockIdx.x >> 5;                      // 32 row-tiles per batch
    int s0 = (blockIdx.x & 31) << 6;

    if (tid < 64) ssc[tid] = 0.f;

    // load 64 rows of A into smem, split to bf16 hi/lo
    const float4* A4 = (const float4*)(Ag + (size_t)(b * S_ + s0) * K);
    for (int i = tid; i < 64 * K / 4; i += 256) {
        float4 v = A4[i];
        int i4 = i * 4;
        int r = i4 / K, c = i4 % K;
        __nv_bfloat16* dH = Ahi + r * AS + c;
        __nv_bfloat16* dL = Alo + r * AS + c;
        __nv_bfloat16 h, l;
        split_bf16(v.x, h, l); dH[0] = h; dL[0] = l;
        split_bf16(v.y, h, l); dH[1] = h; dL[1] = l;
        split_bf16(v.z, h, l); dH[2] = h; dL[2] = l;
        split_bf16(v.w, h, l); dH[3] = h; dL[3] = l;
    }
    __syncthreads();

    int lane = tid & 31, wid = tid >> 5;
    int wm = wid & 1, wn = wid >> 1;              // 2 M-warps x 4 N-warps
    int g = lane >> 2, q = lane & 3;
    float sc[4] = {0.f, 0.f, 0.f, 0.f};

    for (int n0 = 0; n0 < H_; n0 += 128) {
        float acc[2][4][4];
#pragma unroll
        for (int mf = 0; mf < 2; ++mf)
#pragma unroll
            for (int nf = 0; nf < 4; ++nf)
#pragma unroll
                for (int e = 0; e < 4; ++e) acc[mf][nf][e] = 0.f;

        // prefetch k-tile 0 into stage 0
#pragma unroll
        for (int j = 0; j < 2; ++j) {
            int c = tid + 256 * j;
            int nn = c >> 2, seg = c & 3;
            cp_async16(Bhs + nn * 40 + seg * 8, Whi + (size_t)(n0 + nn) * K + seg * 8);
            cp_async16(Bls + nn * 40 + seg * 8, Wlo + (size_t)(n0 + nn) * K + seg * 8);
        }
        cp_commit();

        for (int kt = 0; kt < KT; ++kt) {
            int cur = kt & 1;
            if (kt + 1 < KT) {
                int nxt = cur ^ 1, k0 = (kt + 1) * 32;
#pragma unroll
                for (int j = 0; j < 2; ++j) {
                    int c = tid + 256 * j;
                    int nn = c >> 2, seg = c & 3;
                    cp_async16(Bhs + nxt * 128 * 40 + nn * 40 + seg * 8,
                               Whi + (size_t)(n0 + nn) * K + k0 + seg * 8);
                    cp_async16(Bls + nxt * 128 * 40 + nn * 40 + seg * 8,
                               Wlo + (size_t)(n0 + nn) * K + k0 + seg * 8);
                }
                cp_commit();
                cp_wait1();
            } else {
                cp_wait0();
            }
            __syncthreads();

#pragma unroll
            for (int kf = 0; kf < 2; ++kf) {
                int kb = kt * 32 + kf * 16 + 2 * q;
                unsigned ah[2][4], al[2][4];
#pragma unroll
                for (int mf = 0; mf < 2; ++mf) {
                    int row = wm * 32 + mf * 16 + g;
                    const __nv_bfloat16* pH = Ahi + row * AS + kb;
                    const __nv_bfloat16* pL = Alo + row * AS + kb;
                    ah[mf][0] = *(const unsigned*)(pH);
                    ah[mf][1] = *(const unsigned*)(pH + 8 * AS);
                    ah[mf][2] = *(const unsigned*)(pH + 8);
                    ah[mf][3] = *(const unsigned*)(pH + 8 * AS + 8);
                    al[mf][0] = *(const unsigned*)(pL);
                    al[mf][1] = *(const unsigned*)(pL + 8 * AS);
                    al[mf][2] = *(const unsigned*)(pL + 8);
                    al[mf][3] = *(const unsigned*)(pL + 8 * AS + 8);
                }
#pragma unroll
                for (int nf = 0; nf < 4; ++nf) {
                    int nn = wn * 32 + nf * 8 + g;
                    const __nv_bfloat16* pBh = Bhs + cur * 128 * 40 + nn * 40 + kf * 16 + 2 * q;
                    const __nv_bfloat16* pBl = Bls + cur * 128 * 40 + nn * 40 + kf * 16 + 2 * q;
                    unsigned bh[2], bl[2];
                    bh[0] = *(const unsigned*)(pBh);
                    bh[1] = *(const unsigned*)(pBh + 8);
                    bl[0] = *(const unsigned*)(pBl);
                    bl[1] = *(const unsigned*)(pBl + 8);
#pragma unroll
                    for (int mf = 0; mf < 2; ++mf) {
                        mma_bf16(acc[mf][nf], ah[mf], bh);
                        mma_bf16(acc[mf][nf], ah[mf], bl);
                        mma_bf16(acc[mf][nf], al[mf], bh);
                    }
                }
            }
            __syncthreads();
        }

        // epilogue: tanh(+bias) * avec, fold into per-row score accumulators
#pragma unroll
        for (int nf = 0; nf < 4; ++nf) {
            int n = n0 + wn * 32 + nf * 8 + 2 * q;
            float bi0 = bias[n], bi1 = bias[n + 1];
            float a0 = avec[n], a1 = avec[n + 1];
#pragma unroll
            for (int mf = 0; mf < 2; ++mf) {
                sc[mf * 2 + 0] += tanhf(acc[mf][nf][0] + bi0) * a0 +
                                  tanhf(acc[mf][nf][1] + bi1) * a1;
                sc[mf * 2 + 1] += tanhf(acc[mf][nf][2] + bi0) * a0 +
                                  tanhf(acc[mf][nf][3] + bi1) * a1;
            }
        }
    }

    atomicAdd(&ssc[wm * 32 + g], sc[0]);
    atomicAdd(&ssc[wm * 32 + g + 8], sc[1]);
    atomicAdd(&ssc[wm * 32 + g + 16], sc[2]);
    atomicAdd(&ssc[wm * 32 + g + 24], sc[3]);
    __syncthreads();
    if (tid < 64) {
        float v = ssc[tid];
        float* dst = &g_scores[b * S_ + s0 + tid];
        if (ADD)
            *dst += v;
        else
            *dst = v;
    }
}

// ---------------- kernel 5: combined softmax -> gamma ----------------------
__global__ void softmax_kernel(float* __restrict__ gamma_out) {
    __shared__ float red[256];
    int b = blockIdx.x, tid = threadIdx.x;        // 256 threads
    float v[8];
    float m = -1e30f;
#pragma unroll
    for (int i = 0; i < 8; ++i) {
        v[i] = g_scores[b * S_ + tid + i * 256];
        m = fmaxf(m, v[i]);
    }
    red[tid] = m;
    __syncthreads();
    for (int o = 128; o > 0; o >>= 1) {
        if (tid < o) red[tid] = fmaxf(red[tid], red[tid + o]);
        __syncthreads();
    }
    float M = red[0];
    __syncthreads();
    float s = 0.f;
#pragma unroll
    for (int i = 0; i < 8; ++i) {
        v[i] = expf(v[i] - M);
        s += v[i];
    }
    red[tid] = s;
    __syncthreads();
    for (int o = 128; o > 0; o >>= 1) {
        if (tid < o) red[tid] += red[tid + o];
        __syncthreads();
    }
    float inv = 1.0f / red[0];
#pragma unroll
    for (int i = 0; i < 8; ++i) gamma_out[b * S_ + tid + i * 256] = v[i] * inv;
}

// ---------------- kernel 6: weighted context (streaming, partials) ---------
__global__ void weighted_kernel(const float* __restrict__ ctx,
                                const float* __restrict__ gamma) {
    int scn = blockIdx.x, b = blockIdx.y, tid = threadIdx.x;  // 128 threads
    const float4* C4 = (const float4*)(ctx + (size_t)b * S_ * H_);
    const float* gp = gamma + b * S_ + scn * 256;
    float4 acc = {0.f, 0.f, 0.f, 0.f};
    int base = (scn * 256) * 128 + tid;
#pragma unroll 4
    for (int s = 0; s < 256; ++s) {
        float gv = gp[s];
        float4 v = C4[base + s * 128];
        acc.x += gv * v.x;
        acc.y += gv * v.y;
        acc.z += gv * v.z;
        acc.w += gv * v.w;
    }
    ((float4*)g_wcpart)[(scn * B_ + b) * 128 + tid] = acc;
}

// ---------------- kernel 7: h_tilde = tanh([wc, input] @ W_out) ------------
__global__ void out_kernel(const float* __restrict__ input,
                           const float* __restrict__ W_out,
                           float* __restrict__ out) {
    __shared__ float x[2 * H_];
    int b = blockIdx.x, tid = threadIdx.x;        // 512 threads
    float w = 0.f;
#pragma unroll
    for (int p = 0; p < 8; ++p) w += g_wcpart[(p * B_ + b) * H_ + tid];
    x[tid] = w;
    x[H_ + tid] = input[b * H_ + tid];
    __syncthreads();
    float acc = 0.f;
#pragma unroll 8
    for (int j = 0; j < 2 * H_; ++j) acc += x[j] * W_out[j * H_ + tid];
    out[b * H_ + tid] = tanhf(acc);
}

// ---------------- launch ---------------------------------------------------
extern "C" void kernel_launch(void* const* d_in, const int* in_sizes, int n_in,
                              void* d_out, int out_size) {
    const float* input   = (const float*)d_in[0];
    const float* context = (const float*)d_in[1];
    const float* input_z = (const float*)d_in[2];
    const float* W_enc   = (const float*)d_in[3];
    const float* b_enc   = (const float*)d_in[4];
    const float* W_a     = (const float*)d_in[5];
    const float* b_a     = (const float*)d_in[6];
    const float* W_b     = (const float*)d_in[7];
    const float* b_b     = (const float*)d_in[8];
    const float* W_z     = (const float*)d_in[9];
    const float* b_z     = (const float*)d_in[10];
    const float* W_out   = (const float*)d_in[11];

    float* h_tilde = (float*)d_out;               // [B,H] first
    float* gamma   = (float*)d_out + B_ * H_;     // [B,S] second

    // dynamic smem sizes
    const int SMEM_512 = (2 * 64 * (H_ + 8) + 2 * 2 * 128 * 40) * 2 + 256; // 174336
    const int SMEM_128 = (2 * 64 * (F_ + 8) + 2 * 2 * 128 * 40) * 2 + 256; //  76032
    cudaFuncSetAttribute(score_kernel<H_, 0>,
                         cudaFuncAttributeMaxDynamicSharedMemorySize, SMEM_512);
    cudaFuncSetAttribute(score_kernel<F_, 1>,
                         cudaFuncAttributeMaxDynamicSharedMemorySize, SMEM_128);

    prep_kernel<<<1024, 256>>>(W_enc, W_z);
    proj_in_kernel<<<B_, 256>>>(input, W_a, b_a, W_b, b_b);
    score_kernel<H_, 0><<<B_ * 32, 256, SMEM_512>>>(context, b_enc);
    score_kernel<F_, 1><<<B_ * 32, 256, SMEM_128>>>(input_z, b_z);
    softmax_kernel<<<B_, 256>>>(gamma);
    weighted_kernel<<<dim3(8, B_), 128>>>(context, gamma);
    out_kernel<<<B_, 512>>>(input, W_out, h_tilde);
}

// round 10
// speedup vs baseline: 1.2470x; 1.2470x over previous
#include <cuda_runtime.h>
#include <cuda_bf16.h>
#include <cstdint>
#include <math.h>

#define B_ 64
#define S_ 2048
#define H_ 512
#define F_ 128

// ---------------- persistent device scratch (no allocations allowed) -------
__device__ __align__(16) __nv_bfloat16 g_WencHi[H_ * H_];   // [n][k], k contiguous
__device__ __align__(16) __nv_bfloat16 g_WencLo[H_ * H_];
__device__ __align__(16) __nv_bfloat16 g_WzHi[H_ * F_];     // [n][k]
__device__ __align__(16) __nv_bfloat16 g_WzLo[H_ * F_];
__device__ float g_proj_a[B_ * H_];
__device__ float g_proj_b[B_ * H_];
__device__ float g_scores[B_ * S_];
__device__ float g_wcpart[8 * B_ * H_];       // weighted-context partials

// ---------------- helpers --------------------------------------------------
static __device__ __forceinline__ uint32_t smem_u32(const void* p) {
    uint32_t a;
    asm("{ .reg .u64 t; cvta.to.shared.u64 t, %1; cvt.u32.u64 %0, t; }"
        : "=r"(a) : "l"(p));
    return a;
}

static __device__ __forceinline__ void mma_bf16(float d[4], const unsigned a[4],
                                                const unsigned b[2]) {
    asm volatile(
        "mma.sync.aligned.m16n8k16.row.col.f32.bf16.bf16.f32 "
        "{%0,%1,%2,%3}, {%4,%5,%6,%7}, {%8,%9}, {%0,%1,%2,%3};\n"
        : "+f"(d[0]), "+f"(d[1]), "+f"(d[2]), "+f"(d[3])
        : "r"(a[0]), "r"(a[1]), "r"(a[2]), "r"(a[3]), "r"(b[0]), "r"(b[1]));
}

static __device__ __forceinline__ void ldsm4(unsigned r[4], uint32_t addr) {
    asm volatile("ldmatrix.sync.aligned.m8n8.x4.shared.b16 {%0,%1,%2,%3}, [%4];"
                 : "=r"(r[0]), "=r"(r[1]), "=r"(r[2]), "=r"(r[3]) : "r"(addr));
}

static __device__ __forceinline__ void sts64(uint32_t addr, uint32_t x, uint32_t y) {
    asm volatile("st.shared.v2.b32 [%0], {%1, %2};" ::"r"(addr), "r"(x), "r"(y)
                 : "memory");
}

static __device__ __forceinline__ void cp16(uint32_t dst, const void* src) {
    asm volatile("cp.async.cg.shared.global [%0], [%1], 16;\n" ::"r"(dst), "l"(src));
}
static __device__ __forceinline__ void cp_commit() {
    asm volatile("cp.async.commit_group;\n" ::: "memory");
}
static __device__ __forceinline__ void cp_wait0() {
    asm volatile("cp.async.wait_group 0;\n" ::: "memory");
}

static __device__ __forceinline__ uint32_t pack2(__nv_bfloat16 a, __nv_bfloat16 b) {
    __nv_bfloat162 t = __halves2bfloat162(a, b);
    return *reinterpret_cast<uint32_t*>(&t);
}

static __device__ __forceinline__ void split_bf16(float x, __nv_bfloat16& hi,
                                                  __nv_bfloat16& lo) {
    hi = __float2bfloat16_rn(x);
    lo = __float2bfloat16_rn(x - __bfloat162float(hi));
}

// ---------------- kernel 1: split + transpose weights ----------------------
__global__ void prep_kernel(const float* __restrict__ Wenc,
                            const float* __restrict__ Wz) {
    int idx = blockIdx.x * 256 + threadIdx.x;      // 1024*256 = 262144 = 512*512
    {
        float w = Wenc[idx];                       // [k][n] row-major
        __nv_bfloat16 hi, lo;
        split_bf16(w, hi, lo);
        int k = idx >> 9, n = idx & 511;
        g_WencHi[n * H_ + k] = hi;
        g_WencLo[n * H_ + k] = lo;
    }
    if (idx < F_ * H_) {                           // Wz [f][n]
        float w = Wz[idx];
        __nv_bfloat16 hi, lo;
        split_bf16(w, hi, lo);
        int f = idx >> 9, n = idx & 511;
        g_WzHi[n * F_ + f] = hi;
        g_WzLo[n * F_ + f] = lo;
    }
}

// ---------------- kernel 2: proj_in_a / proj_in_b --------------------------
__global__ void proj_in_kernel(const float* __restrict__ input,
                               const float* __restrict__ W_a,
                               const float* __restrict__ b_a,
                               const float* __restrict__ W_b,
                               const float* __restrict__ b_b) {
    __shared__ float x[H_];
    int b = blockIdx.x, tid = threadIdx.x;         // 256 threads
    x[tid] = input[b * H_ + tid];
    x[tid + 256] = input[b * H_ + tid + 256];
    __syncthreads();
    for (int h = tid; h < H_; h += 256) {
        float aa = 0.f, ab = 0.f;
#pragma unroll 8
        for (int j = 0; j < H_; ++j) {
            float xv = x[j];
            aa += xv * W_a[j * H_ + h];
            ab += xv * W_b[j * H_ + h];
        }
        g_proj_a[b * H_ + h] = tanhf(aa + b_a[h]);
        g_proj_b[b * H_ + h] = tanhf(ab + b_b[h]);
    }
}

// ---------------- kernels 3/4: fused score via mma.sync + ldmatrix ---------
// Per block: 64 rows x full H, n-passes of 128 cols, K streamed in 64-chunks,
// double-buffered SMEM (48KB/stage), 2 CTAs/SM. 3-term bf16 split precision.
// Stage layout: Ahi[64x64]=8K | Alo=8K | Bhi[128x64]=16K | Blo=16K  (SW128)
template <int KTOT, int ADD>
__global__ void __launch_bounds__(256, 2)
score_mma_kernel(const float* __restrict__ Ag,     // [B][S][KTOT] fp32
                 const float* __restrict__ bias) { // [H]
    constexpr int NCHUNK = KTOT / 64;
    extern __shared__ char smem_raw[];
    __shared__ float ssc[64];
    const uint32_t sb = smem_u32(smem_raw);

    const int tid = threadIdx.x;
    const int lane = tid & 31, wid = tid >> 5;
    const int wm = wid & 1, wn = wid >> 1;        // 2 M-warps x 4 N-warps
    const int g = lane >> 2, q = lane & 3;

    const int b = blockIdx.x >> 5;                // 32 row-tiles per batch
    const int s0 = (blockIdx.x & 31) << 6;

    const __nv_bfloat16* __restrict__ Whi = (KTOT == H_) ? g_WencHi : g_WzHi;
    const __nv_bfloat16* __restrict__ Wlo = (KTOT == H_) ? g_WencLo : g_WzLo;
    const float* __restrict__ avec =
        ((KTOT == H_) ? g_proj_a : g_proj_b) + b * H_;

    if (tid < 64) ssc[tid] = 0.f;

    // A loader mapping: 4 threads/row, each 16 fp32 (4x float4)
    const int ar = tid >> 2, acq = (tid & 3) * 16;
    const float* aG = Ag + (size_t)(b * S_ + s0 + ar) * KTOT + acq;
    const uint32_t swa = (uint32_t)((ar & 7) << 4);
    const uint32_t aRow = (uint32_t)(ar * 128);
    // B loader mapping: 2 threads/row, each 4x 16B segments (hi and lo)
    const int bn = tid >> 1, bseg0 = (tid & 1) * 4;
    const uint32_t swb = (uint32_t)((bn & 7) << 4);
    const uint32_t bRow = (uint32_t)(bn * 128);

    // ldmatrix per-lane constants
    const uint32_t swl = (uint32_t)((lane & 7) << 4);
    const uint32_t rowA0 = (uint32_t)((wm * 32 + (lane & 15)) * 128);
    const uint32_t rowA1 = rowA0 + 16 * 128;
    const uint32_t klA = (uint32_t)((lane >> 4) << 4);
    const uint32_t rowB0 =
        (uint32_t)((wn * 32 + (lane & 7) + ((lane >> 4) << 3)) * 128);
    const uint32_t rowB1 = rowB0 + 16 * 128;
    const uint32_t klB = (uint32_t)(((lane >> 3) & 1) << 4);

    float sc[4] = {0.f, 0.f, 0.f, 0.f};

    for (int p = 0; p < 4; ++p) {
        const int n0 = p * 128;
        float acc[2][4][4];
#pragma unroll
        for (int mf = 0; mf < 2; ++mf)
#pragma unroll
            for (int nf = 0; nf < 4; ++nf)
#pragma unroll
                for (int e = 0; e < 4; ++e) acc[mf][nf][e] = 0.f;

        // ---- prologue: chunk 0 -> stage 0
        {
            float4 va[4];
#pragma unroll
            for (int j = 0; j < 4; ++j) va[j] = *(const float4*)(aG + j * 4);
            uint32_t bB = sb + 16384;
            const __nv_bfloat16* shh =
                Whi + (size_t)(n0 + bn) * KTOT + bseg0 * 8;
            const __nv_bfloat16* sll =
                Wlo + (size_t)(n0 + bn) * KTOT + bseg0 * 8;
#pragma unroll
            for (int j = 0; j < 4; ++j) {
                uint32_t off = bRow + (((uint32_t)((bseg0 + j) * 16)) ^ swb);
                cp16(bB + off, shh + j * 8);
                cp16(bB + 16384 + off, sll + j * 8);
            }
            cp_commit();
#pragma unroll
            for (int j = 0; j < 4; ++j) {
                __nv_bfloat16 hx, lx, hy, ly, hz, lz, hw, lw;
                split_bf16(va[j].x, hx, lx);
                split_bf16(va[j].y, hy, ly);
                split_bf16(va[j].z, hz, lz);
                split_bf16(va[j].w, hw, lw);
                uint32_t off = aRow + (((uint32_t)(acq * 2 + j * 8)) ^ swa);
                sts64(sb + off, pack2(hx, hy), pack2(hz, hw));
                sts64(sb + 8192 + off, pack2(lx, ly), pack2(lz, lw));
            }
            cp_wait0();
        }
        __syncthreads();

        for (int c = 0; c < NCHUNK; ++c) {
            const uint32_t st = (uint32_t)(c & 1);
            const bool pre = (c + 1 < NCHUNK);
            float4 va[4];
            if (pre) {
                const int k0n = (c + 1) * 64;
#pragma unroll
                for (int j = 0; j < 4; ++j)
                    va[j] = *(const float4*)(aG + k0n + j * 4);
                uint32_t bB = sb + (st ^ 1u) * 49152u + 16384u;
                const __nv_bfloat16* shh =
                    Whi + (size_t)(n0 + bn) * KTOT + k0n + bseg0 * 8;
                const __nv_bfloat16* sll =
                    Wlo + (size_t)(n0 + bn) * KTOT + k0n + bseg0 * 8;
#pragma unroll
                for (int j = 0; j < 4; ++j) {
                    uint32_t off =
                        bRow + (((uint32_t)((bseg0 + j) * 16)) ^ swb);
                    cp16(bB + off, shh + j * 8);
                    cp16(bB + 16384 + off, sll + j * 8);
                }
                cp_commit();
            }

            // ---- compute on stage st
            {
                const uint32_t aB = sb + st * 49152u;
                const uint32_t bB = aB + 16384u;
#pragma unroll
                for (int kf = 0; kf < 4; ++kf) {
                    const uint32_t cA = (((uint32_t)(kf * 32)) + klA) ^ swl;
                    const uint32_t cB = (((uint32_t)(kf * 32)) + klB) ^ swl;
                    unsigned ah0[4], ah1[4], al0[4], al1[4];
                    ldsm4(ah0, aB + rowA0 + cA);
                    ldsm4(ah1, aB + rowA1 + cA);
                    ldsm4(al0, aB + 8192 + rowA0 + cA);
                    ldsm4(al1, aB + 8192 + rowA1 + cA);
#pragma unroll
                    for (int nfp = 0; nfp < 2; ++nfp) {
                        unsigned bh[4], bl[4];
                        const uint32_t rB = nfp ? rowB1 : rowB0;
                        ldsm4(bh, bB + rB + cB);
                        ldsm4(bl, bB + 16384 + rB + cB);
                        const int nf = 2 * nfp;
                        mma_bf16(acc[0][nf], ah0, bh + 0);
                        mma_bf16(acc[0][nf], ah0, bl + 0);
                        mma_bf16(acc[0][nf], al0, bh + 0);
                        mma_bf16(acc[1][nf], ah1, bh + 0);
                        mma_bf16(acc[1][nf], ah1, bl + 0);
                        mma_bf16(acc[1][nf], al1, bh + 0);
                        mma_bf16(acc[0][nf + 1], ah0, bh + 2);
                        mma_bf16(acc[0][nf + 1], ah0, bl + 2);
                        mma_bf16(acc[0][nf + 1], al0, bh + 2);
                        mma_bf16(acc[1][nf + 1], ah1, bh + 2);
                        mma_bf16(acc[1][nf + 1], ah1, bl + 2);
                        mma_bf16(acc[1][nf + 1], al1, bh + 2);
                    }
                }
            }

            if (pre) {
                uint32_t aBn = sb + (st ^ 1u) * 49152u;
#pragma unroll
                for (int j = 0; j < 4; ++j) {
                    __nv_bfloat16 hx, lx, hy, ly, hz, lz, hw, lw;
                    split_bf16(va[j].x, hx, lx);
                    split_bf16(va[j].y, hy, ly);
                    split_bf16(va[j].z, hz, lz);
                    split_bf16(va[j].w, hw, lw);
                    uint32_t off =
                        aRow + (((uint32_t)(acq * 2 + j * 8)) ^ swa);
                    sts64(aBn + off, pack2(hx, hy), pack2(hz, hw));
                    sts64(aBn + 8192 + off, pack2(lx, ly), pack2(lz, lw));
                }
                cp_wait0();
            }
            __syncthreads();
        }

        // ---- epilogue: fold tanh(+bias)*avec into per-row score regs
#pragma unroll
        for (int nf = 0; nf < 4; ++nf) {
            int n = n0 + wn * 32 + nf * 8 + 2 * q;
            float bi0 = bias[n], bi1 = bias[n + 1];
            float a0 = avec[n], a1 = avec[n + 1];
#pragma unroll
            for (int mf = 0; mf < 2; ++mf) {
                sc[mf * 2 + 0] += tanhf(acc[mf][nf][0] + bi0) * a0 +
                                  tanhf(acc[mf][nf][1] + bi1) * a1;
                sc[mf * 2 + 1] += tanhf(acc[mf][nf][2] + bi0) * a0 +
                                  tanhf(acc[mf][nf][3] + bi1) * a1;
            }
        }
    }

    // reduce over q lanes (same row, different n columns)
#pragma unroll
    for (int j = 0; j < 4; ++j) {
        sc[j] += __shfl_xor_sync(0xFFFFFFFFu, sc[j], 1);
        sc[j] += __shfl_xor_sync(0xFFFFFFFFu, sc[j], 2);
    }
    if (q == 0) {
#pragma unroll
        for (int mf = 0; mf < 2; ++mf)
#pragma unroll
            for (int hb = 0; hb < 2; ++hb)
                atomicAdd(&ssc[wm * 32 + mf * 16 + hb * 8 + g],
                          sc[mf * 2 + hb]);
    }
    __syncthreads();
    if (tid < 64) {
        float v = ssc[tid];
        float* dst = &g_scores[b * S_ + s0 + tid];
        if (ADD)
            *dst += v;
        else
            *dst = v;
    }
}

// ---------------- kernel 5: combined softmax -> gamma ----------------------
__global__ void softmax_kernel(float* __restrict__ gamma_out) {
    __shared__ float red[256];
    int b = blockIdx.x, tid = threadIdx.x;        // 256 threads
    float v[8];
    float m = -1e30f;
#pragma unroll
    for (int i = 0; i < 8; ++i) {
        v[i] = g_scores[b * S_ + tid + i * 256];
        m = fmaxf(m, v[i]);
    }
    red[tid] = m;
    __syncthreads();
    for (int o = 128; o > 0; o >>= 1) {
        if (tid < o) red[tid] = fmaxf(red[tid], red[tid + o]);
        __syncthreads();
    }
    float M = red[0];
    __syncthreads();
    float s = 0.f;
#pragma unroll
    for (int i = 0; i < 8; ++i) {
        v[i] = expf(v[i] - M);
        s += v[i];
    }
    red[tid] = s;
    __syncthreads();
    for (int o = 128; o > 0; o >>= 1) {
        if (tid < o) red[tid] += red[tid + o];
        __syncthreads();
    }
    float inv = 1.0f / red[0];
#pragma unroll
    for (int i = 0; i < 8; ++i) gamma_out[b * S_ + tid + i * 256] = v[i] * inv;
}

// ---------------- kernel 6: weighted context --------------------------------
__global__ void weighted_kernel(const float* __restrict__ ctx,
                                const float* __restrict__ gamma) {
    int scn = blockIdx.x, b = blockIdx.y, tid = threadIdx.x;  // 128 threads
    const float4* C4 = (const float4*)(ctx + (size_t)b * S_ * H_);
    const float* gp = gamma + b * S_ + scn * 256;
    float4 acc = {0.f, 0.f, 0.f, 0.f};
    int base = (scn * 256) * 128 + tid;
#pragma unroll 4
    for (int s = 0; s < 256; ++s) {
        float gv = gp[s];
        float4 v = C4[base + s * 128];
        acc.x += gv * v.x;
        acc.y += gv * v.y;
        acc.z += gv * v.z;
        acc.w += gv * v.w;
    }
    ((float4*)g_wcpart)[(scn * B_ + b) * 128 + tid] = acc;
}

// ---------------- kernel 7: h_tilde -----------------------------------------
__global__ void out_kernel(const float* __restrict__ input,
                           const float* __restrict__ W_out,
                           float* __restrict__ out) {
    __shared__ float x[2 * H_];
    int b = blockIdx.x, tid = threadIdx.x;        // 512 threads
    float w = 0.f;
#pragma unroll
    for (int p = 0; p < 8; ++p) w += g_wcpart[(p * B_ + b) * H_ + tid];
    x[tid] = w;
    x[H_ + tid] = input[b * H_ + tid];
    __syncthreads();
    float acc = 0.f;
#pragma unroll 8
    for (int j = 0; j < 2 * H_; ++j) acc += x[j] * W_out[j * H_ + tid];
    out[b * H_ + tid] = tanhf(acc);
}

// ---------------- launch ----------------------------------------------------
extern "C" void kernel_launch(void* const* d_in, const int* in_sizes, int n_in,
                              void* d_out, int out_size) {
    const float* input   = (const float*)d_in[0];
    const float* context = (const float*)d_in[1];
    const float* input_z = (const float*)d_in[2];
    const float* W_enc   = (const float*)d_in[3];
    const float* b_enc   = (const float*)d_in[4];
    const float* W_a     = (const float*)d_in[5];
    const float* b_a     = (const float*)d_in[6];
    const float* W_b     = (const float*)d_in[7];
    const float* b_b     = (const float*)d_in[8];
    const float* W_z     = (const float*)d_in[9];
    const float* b_z     = (const float*)d_in[10];
    const float* W_out   = (const float*)d_in[11];

    float* h_tilde = (float*)d_out;               // [B,H] first
    float* gamma   = (float*)d_out + B_ * H_;     // [B,S] second

    const int SMEM_SC = 2 * 49152;                // 96KB (two 48KB stages)
    cudaFuncSetAttribute(score_mma_kernel<H_, 0>,
                         cudaFuncAttributeMaxDynamicSharedMemorySize, SMEM_SC);
    cudaFuncSetAttribute(score_mma_kernel<F_, 1>,
                         cudaFuncAttributeMaxDynamicSharedMemorySize, SMEM_SC);

    prep_kernel<<<1024, 256>>>(W_enc, W_z);
    proj_in_kernel<<<B_, 256>>>(input, W_a, b_a, W_b, b_b);
    score_mma_kernel<H_, 0><<<B_ * 32, 256, SMEM_SC>>>(context, b_enc);
    score_mma_kernel<F_, 1><<<B_ * 32, 256, SMEM_SC>>>(input_z, b_z);
    softmax_kernel<<<B_, 256>>>(gamma);
    weighted_kernel<<<dim3(8, B_), 128>>>(context, gamma);
    out_kernel<<<B_, 512>>>(input, W_out, h_tilde);
}

// round 12
// speedup vs baseline: 1.5001x; 1.2030x over previous
#include <cuda_runtime.h>
#include <cuda_fp16.h>
#include <cstdint>
#include <math.h>

#define B_ 64
#define S_ 2048
#define H_ 512
#define F_ 128

// ---------------- persistent device scratch (no allocations allowed) -------
__device__ __align__(16) __half g_WencHi[H_ * H_];   // [n][k], k contiguous
__device__ __align__(16) __half g_WencLo[H_ * H_];
__device__ __align__(16) __half g_WzHi[H_ * F_];     // [n][k]
__device__ __align__(16) __half g_WzLo[H_ * F_];
__device__ float g_proj_a[B_ * H_];
__device__ float g_proj_b[B_ * H_];
__device__ float g_scores[B_ * S_];
__device__ float g_wcpart[8 * B_ * H_];       // weighted-context partials

// ---------------- helpers --------------------------------------------------
static __device__ __forceinline__ uint32_t smem_u32(const void* p) {
    uint32_t a;
    asm("{ .reg .u64 t; cvta.to.shared.u64 t, %1; cvt.u32.u64 %0, t; }"
        : "=r"(a) : "l"(p));
    return a;
}

static __device__ __forceinline__ void mma_f16(float d[4], const unsigned a[4],
                                               const unsigned b[2]) {
    asm volatile(
        "mma.sync.aligned.m16n8k16.row.col.f32.f16.f16.f32 "
        "{%0,%1,%2,%3}, {%4,%5,%6,%7}, {%8,%9}, {%0,%1,%2,%3};\n"
        : "+f"(d[0]), "+f"(d[1]), "+f"(d[2]), "+f"(d[3])
        : "r"(a[0]), "r"(a[1]), "r"(a[2]), "r"(a[3]), "r"(b[0]), "r"(b[1]));
}

static __device__ __forceinline__ void ldsm4(unsigned r[4], uint32_t addr) {
    asm volatile("ldmatrix.sync.aligned.m8n8.x4.shared.b16 {%0,%1,%2,%3}, [%4];"
                 : "=r"(r[0]), "=r"(r[1]), "=r"(r[2]), "=r"(r[3]) : "r"(addr));
}

static __device__ __forceinline__ void sts64(uint32_t addr, uint32_t x, uint32_t y) {
    asm volatile("st.shared.v2.b32 [%0], {%1, %2};" ::"r"(addr), "r"(x), "r"(y)
                 : "memory");
}

static __device__ __forceinline__ void cp16(uint32_t dst, const void* src) {
    asm volatile("cp.async.cg.shared.global [%0], [%1], 16;\n" ::"r"(dst), "l"(src));
}
static __device__ __forceinline__ void cp_commit() {
    asm volatile("cp.async.commit_group;\n" ::: "memory");
}
static __device__ __forceinline__ void cp_wait0() {
    asm volatile("cp.async.wait_group 0;\n" ::: "memory");
}

static __device__ __forceinline__ uint32_t pack2h(float a, float b) {
    __half2 t = __floats2half2_rn(a, b);
    return *reinterpret_cast<uint32_t*>(&t);
}

static __device__ __forceinline__ void split_f16(float x, __half& hi, __half& lo) {
    hi = __float2half_rn(x);
    lo = __float2half_rn(x - __half2float(hi));
}

// ---------------- kernel 1: split + transpose weights ----------------------
__global__ void prep_kernel(const float* __restrict__ Wenc,
                            const float* __restrict__ Wz) {
    int idx = blockIdx.x * 256 + threadIdx.x;      // 1024*256 = 262144 = 512*512
    {
        float w = Wenc[idx];                       // [k][n] row-major
        __half hi, lo;
        split_f16(w, hi, lo);
        int k = idx >> 9, n = idx & 511;
        g_WencHi[n * H_ + k] = hi;
        g_WencLo[n * H_ + k] = lo;
    }
    if (idx < F_ * H_) {                           // Wz [f][n]
        float w = Wz[idx];
        __half hi, lo;
        split_f16(w, hi, lo);
        int f = idx >> 9, n = idx & 511;
        g_WzHi[n * F_ + f] = hi;
        g_WzLo[n * F_ + f] = lo;
    }
}

// ---------------- kernel 2: proj_in_a / proj_in_b --------------------------
__global__ void proj_in_kernel(const float* __restrict__ input,
                               const float* __restrict__ W_a,
                               const float* __restrict__ b_a,
                               const float* __restrict__ W_b,
                               const float* __restrict__ b_b) {
    __shared__ float x[H_];
    int b = blockIdx.x, tid = threadIdx.x;         // 256 threads
    x[tid] = input[b * H_ + tid];
    x[tid + 256] = input[b * H_ + tid + 256];
    __syncthreads();
    for (int h = tid; h < H_; h += 256) {
        float aa = 0.f, ab = 0.f;
#pragma unroll 8
        for (int j = 0; j < H_; ++j) {
            float xv = x[j];
            aa += xv * W_a[j * H_ + h];
            ab += xv * W_b[j * H_ + h];
        }
        g_proj_a[b * H_ + h] = tanhf(aa + b_a[h]);
        g_proj_b[b * H_ + h] = tanhf(ab + b_b[h]);
    }
}

// ---------------- kernels 3/4: fused score via mma.sync + ldmatrix ---------
// Per block: 64 rows x full H, n-passes of 128 cols, K streamed in 64-chunks,
// double-buffered SMEM (40KB/stage), 2 CTAs/SM.
// Precision: A single fp16, B split fp16 (hi+lo) -> C = A*(Bh+Bl), fp32 acc.
// Stage layout: A[64x64]=8K | Bhi[128x64]=16K | Blo=16K   (SW128 swizzle)
template <int KTOT, int ADD>
__global__ void __launch_bounds__(256, 2)
score_mma_kernel(const float* __restrict__ Ag,     // [B][S][KTOT] fp32
                 const float* __restrict__ bias) { // [H]
    constexpr int NCHUNK = KTOT / 64;
    constexpr uint32_t STAGE = 40960u;
    constexpr uint32_t BH_OFF = 8192u;
    constexpr uint32_t BL_OFF = 24576u;
    extern __shared__ char smem_raw[];
    __shared__ float ssc[64];
    const uint32_t sb = smem_u32(smem_raw);

    const int tid = threadIdx.x;
    const int lane = tid & 31, wid = tid >> 5;
    const int wm = wid & 1, wn = wid >> 1;        // 2 M-warps x 4 N-warps
    const int g = lane >> 2, q = lane & 3;

    const int b = blockIdx.x >> 5;                // 32 row-tiles per batch
    const int s0 = (blockIdx.x & 31) << 6;

    const __half* __restrict__ Whi = (KTOT == H_) ? g_WencHi : g_WzHi;
    const __half* __restrict__ Wlo = (KTOT == H_) ? g_WencLo : g_WzLo;
    const float* __restrict__ avec =
        ((KTOT == H_) ? g_proj_a : g_proj_b) + b * H_;

    if (tid < 64) ssc[tid] = 0.f;

    // A loader mapping: 4 threads/row, each 16 fp32 (4x float4)
    const int ar = tid >> 2, acq = (tid & 3) * 16;
    const float* aG = Ag + (size_t)(b * S_ + s0 + ar) * KTOT + acq;
    const uint32_t swa = (uint32_t)((ar & 7) << 4);
    const uint32_t aRow = (uint32_t)(ar * 128);
    // B loader mapping: 2 threads/row, each 4x 16B segments (hi and lo)
    const int bn = tid >> 1, bseg0 = (tid & 1) * 4;
    const uint32_t swb = (uint32_t)((bn & 7) << 4);
    const uint32_t bRow = (uint32_t)(bn * 128);

    // ldmatrix per-lane constants
    const uint32_t swl = (uint32_t)((lane & 7) << 4);
    const uint32_t rowA0 = (uint32_t)((wm * 32 + (lane & 15)) * 128);
    const uint32_t rowA1 = rowA0 + 16 * 128;
    const uint32_t klA = (uint32_t)((lane >> 4) << 4);
    const uint32_t rowB0 =
        (uint32_t)((wn * 32 + (lane & 7) + ((lane >> 4) << 3)) * 128);
    const uint32_t rowB1 = rowB0 + 16 * 128;
    const uint32_t klB = (uint32_t)(((lane >> 3) & 1) << 4);

    float sc[4] = {0.f, 0.f, 0.f, 0.f};

    for (int p = 0; p < 4; ++p) {
        const int n0 = p * 128;
        float acc[2][4][4];
#pragma unroll
        for (int mf = 0; mf < 2; ++mf)
#pragma unroll
            for (int nf = 0; nf < 4; ++nf)
#pragma unroll
                for (int e = 0; e < 4; ++e) acc[mf][nf][e] = 0.f;

        // ---- prologue: chunk 0 -> stage 0
        {
            float4 va[4];
#pragma unroll
            for (int j = 0; j < 4; ++j) va[j] = *(const float4*)(aG + j * 4);
            const __half* shh = Whi + (size_t)(n0 + bn) * KTOT + bseg0 * 8;
            const __half* sll = Wlo + (size_t)(n0 + bn) * KTOT + bseg0 * 8;
#pragma unroll
            for (int j = 0; j < 4; ++j) {
                uint32_t off = bRow + (((uint32_t)((bseg0 + j) * 16)) ^ swb);
                cp16(sb + BH_OFF + off, shh + j * 8);
                cp16(sb + BL_OFF + off, sll + j * 8);
            }
            cp_commit();
#pragma unroll
            for (int j = 0; j < 4; ++j) {
                uint32_t off = aRow + (((uint32_t)(acq * 2 + j * 8)) ^ swa);
                sts64(sb + off, pack2h(va[j].x, va[j].y),
                      pack2h(va[j].z, va[j].w));
            }
            cp_wait0();
        }
        __syncthreads();

        for (int c = 0; c < NCHUNK; ++c) {
            const uint32_t st = (uint32_t)(c & 1);
            const bool pre = (c + 1 < NCHUNK);
            float4 va[4];
            if (pre) {
                const int k0n = (c + 1) * 64;
#pragma unroll
                for (int j = 0; j < 4; ++j)
                    va[j] = *(const float4*)(aG + k0n + j * 4);
                uint32_t bB = sb + (st ^ 1u) * STAGE;
                const __half* shh =
                    Whi + (size_t)(n0 + bn) * KTOT + k0n + bseg0 * 8;
                const __half* sll =
                    Wlo + (size_t)(n0 + bn) * KTOT + k0n + bseg0 * 8;
#pragma unroll
                for (int j = 0; j < 4; ++j) {
                    uint32_t off =
                        bRow + (((uint32_t)((bseg0 + j) * 16)) ^ swb);
                    cp16(bB + BH_OFF + off, shh + j * 8);
                    cp16(bB + BL_OFF + off, sll + j * 8);
                }
                cp_commit();
            }

            // ---- compute on stage st
            {
                const uint32_t aB = sb + st * STAGE;
                const uint32_t bBh = aB + BH_OFF;
                const uint32_t bBl = aB + BL_OFF;
#pragma unroll
                for (int kf = 0; kf < 4; ++kf) {
                    const uint32_t cA = (((uint32_t)(kf * 32)) + klA) ^ swl;
                    const uint32_t cB = (((uint32_t)(kf * 32)) + klB) ^ swl;
                    unsigned ah0[4], ah1[4];
                    ldsm4(ah0, aB + rowA0 + cA);
                    ldsm4(ah1, aB + rowA1 + cA);
#pragma unroll
                    for (int nfp = 0; nfp < 2; ++nfp) {
                        unsigned bh[4], bl[4];
                        const uint32_t rB = nfp ? rowB1 : rowB0;
                        ldsm4(bh, bBh + rB + cB);
                        ldsm4(bl, bBl + rB + cB);
                        const int nf = 2 * nfp;
                        mma_f16(acc[0][nf], ah0, bh + 0);
                        mma_f16(acc[0][nf], ah0, bl + 0);
                        mma_f16(acc[1][nf], ah1, bh + 0);
                        mma_f16(acc[1][nf], ah1, bl + 0);
                        mma_f16(acc[0][nf + 1], ah0, bh + 2);
                        mma_f16(acc[0][nf + 1], ah0, bl + 2);
                        mma_f16(acc[1][nf + 1], ah1, bh + 2);
                        mma_f16(acc[1][nf + 1], ah1, bl + 2);
                    }
                }
            }

            if (pre) {
                uint32_t aBn = sb + (st ^ 1u) * STAGE;
#pragma unroll
                for (int j = 0; j < 4; ++j) {
                    uint32_t off =
                        aRow + (((uint32_t)(acq * 2 + j * 8)) ^ swa);
                    sts64(aBn + off, pack2h(va[j].x, va[j].y),
                          pack2h(va[j].z, va[j].w));
                }
                cp_wait0();
            }
            __syncthreads();
        }

        // ---- epilogue: fold tanh(+bias)*avec into per-row score regs
#pragma unroll
        for (int nf = 0; nf < 4; ++nf) {
            int n = n0 + wn * 32 + nf * 8 + 2 * q;
            float bi0 = bias[n], bi1 = bias[n + 1];
            float a0 = avec[n], a1 = avec[n + 1];
#pragma unroll
            for (int mf = 0; mf < 2; ++mf) {
                sc[mf * 2 + 0] += tanhf(acc[mf][nf][0] + bi0) * a0 +
                                  tanhf(acc[mf][nf][1] + bi1) * a1;
                sc[mf * 2 + 1] += tanhf(acc[mf][nf][2] + bi0) * a0 +
                                  tanhf(acc[mf][nf][3] + bi1) * a1;
            }
        }
    }

    // reduce over q lanes (same row, different n columns)
#pragma unroll
    for (int j = 0; j < 4; ++j) {
        sc[j] += __shfl_xor_sync(0xFFFFFFFFu, sc[j], 1);
        sc[j] += __shfl_xor_sync(0xFFFFFFFFu, sc[j], 2);
    }
    if (q == 0) {
#pragma unroll
        for (int mf = 0; mf < 2; ++mf)
#pragma unroll
            for (int hb = 0; hb < 2; ++hb)
                atomicAdd(&ssc[wm * 32 + mf * 16 + hb * 8 + g],
                          sc[mf * 2 + hb]);
    }
    __syncthreads();
    if (tid < 64) {
        float v = ssc[tid];
        float* dst = &g_scores[b * S_ + s0 + tid];
        if (ADD)
            *dst += v;
        else
            *dst = v;
    }
}

// ---------------- kernel 5: combined softmax -> gamma ----------------------
__global__ void softmax_kernel(float* __restrict__ gamma_out) {
    __shared__ float red[256];
    int b = blockIdx.x, tid = threadIdx.x;        // 256 threads
    float v[8];
    float m = -1e30f;
#pragma unroll
    for (int i = 0; i < 8; ++i) {
        v[i] = g_scores[b * S_ + tid + i * 256];
        m = fmaxf(m, v[i]);
    }
    red[tid] = m;
    __syncthreads();
    for (int o = 128; o > 0; o >>= 1) {
        if (tid < o) red[tid] = fmaxf(red[tid], red[tid + o]);
        __syncthreads();
    }
    float M = red[0];
    __syncthreads();
    float s = 0.f;
#pragma unroll
    for (int i = 0; i < 8; ++i) {
        v[i] = expf(v[i] - M);
        s += v[i];
    }
    red[tid] = s;
    __syncthreads();
    for (int o = 128; o > 0; o >>= 1) {
        if (tid < o) red[tid] += red[tid + o];
        __syncthreads();
    }
    float inv = 1.0f / red[0];
#pragma unroll
    for (int i = 0; i < 8; ++i) gamma_out[b * S_ + tid + i * 256] = v[i] * inv;
}

// ---------------- kernel 6: weighted context --------------------------------
__global__ void weighted_kernel(const float* __restrict__ ctx,
                                const float* __restrict__ gamma) {
    int scn = blockIdx.x, b = blockIdx.y, tid = threadIdx.x;  // 128 threads
    const float4* C4 = (const float4*)(ctx + (size_t)b * S_ * H_);
    const float* gp = gamma + b * S_ + scn * 256;
    float4 acc = {0.f, 0.f, 0.f, 0.f};
    int base = (scn * 256) * 128 + tid;
#pragma unroll 4
    for (int s = 0; s < 256; ++s) {
        float gv = gp[s];
        float4 v = C4[base + s * 128];
        acc.x += gv * v.x;
        acc.y += gv * v.y;
        acc.z += gv * v.z;
        acc.w += gv * v.w;
    }
    ((float4*)g_wcpart)[(scn * B_ + b) * 128 + tid] = acc;
}

// ---------------- kernel 7: h_tilde -----------------------------------------
__global__ void out_kernel(const float* __restrict__ input,
                           const float* __restrict__ W_out,
                           float* __restrict__ out) {
    __shared__ float x[2 * H_];
    int b = blockIdx.x, tid = threadIdx.x;        // 512 threads
    float w = 0.f;
#pragma unroll
    for (int p = 0; p < 8; ++p) w += g_wcpart[(p * B_ + b) * H_ + tid];
    x[tid] = w;
    x[H_ + tid] = input[b * H_ + tid];
    __syncthreads();
    float acc = 0.f;
#pragma unroll 8
    for (int j = 0; j < 2 * H_; ++j) acc += x[j] * W_out[j * H_ + tid];
    out[b * H_ + tid] = tanhf(acc);
}

// ---------------- launch ----------------------------------------------------
extern "C" void kernel_launch(void* const* d_in, const int* in_sizes, int n_in,
                              void* d_out, int out_size) {
    const float* input   = (const float*)d_in[0];
    const float* context = (const float*)d_in[1];
    const float* input_z = (const float*)d_in[2];
    const float* W_enc   = (const float*)d_in[3];
    const float* b_enc   = (const float*)d_in[4];
    const float* W_a     = (const float*)d_in[5];
    const float* b_a     = (const float*)d_in[6];
    const float* W_b     = (const float*)d_in[7];
    const float* b_b     = (const float*)d_in[8];
    const float* W_z     = (const float*)d_in[9];
    const float* b_z     = (const float*)d_in[10];
    const float* W_out   = (const float*)d_in[11];

    float* h_tilde = (float*)d_out;               // [B,H] first
    float* gamma   = (float*)d_out + B_ * H_;     // [B,S] second

    const int SMEM_SC = 2 * 40960;                // 80KB (two 40KB stages)
    cudaFuncSetAttribute(score_mma_kernel<H_, 0>,
                         cudaFuncAttributeMaxDynamicSharedMemorySize, SMEM_SC);
    cudaFuncSetAttribute(score_mma_kernel<F_, 1>,
                         cudaFuncAttributeMaxDynamicSharedMemorySize, SMEM_SC);

    prep_kernel<<<1024, 256>>>(W_enc, W_z);
    proj_in_kernel<<<B_, 256>>>(input, W_a, b_a, W_b, b_b);
    score_mma_kernel<H_, 0><<<B_ * 32, 256, SMEM_SC>>>(context, b_enc);
    score_mma_kernel<F_, 1><<<B_ * 32, 256, SMEM_SC>>>(input_z, b_z);
    softmax_kernel<<<B_, 256>>>(gamma);
    weighted_kernel<<<dim3(8, B_), 128>>>(context, gamma);
    out_kernel<<<B_, 512>>>(input, W_out, h_tilde);
}